// round 2
// baseline (speedup 1.0000x reference)
#include <cuda_runtime.h>
#include <cstdint>

// Problem constants (validated against in_sizes at launch)
#define NN 50000
#define IC 128
#define OC 64

// ---------------- device scratch (static, allocation-free) ----------------
__device__ float g_dinv[NN];            // deg -> dinv in place
__device__ float g_h[(size_t)NN * 128]; // transformed features per conv
__device__ float g_a[(size_t)NN * 128]; // aggregated output per conv
__device__ float g_z[(size_t)NN * 64];  // latent z

// ---------------- degree / normalization ----------------
__global__ void k_deg_init(int n) {
    int i = blockIdx.x * blockDim.x + threadIdx.x;
    if (i < n) g_dinv[i] = 1.0f;  // self-loop contributes 1
}

__global__ void k_deg_count(const int* __restrict__ dst, int e) {
    int i = blockIdx.x * blockDim.x + threadIdx.x;
    if (i < e) atomicAdd(&g_dinv[dst[i]], 1.0f);
}

__global__ void k_dinv(int n) {
    int i = blockIdx.x * blockDim.x + threadIdx.x;
    if (i < n) g_dinv[i] = rsqrtf(g_dinv[i]);  // deg >= 1 always (self loop)
}

// ---------------- GEMM: out[n,COUT] = act(x)[n,CIN] @ W[CIN,COUT] (+bias) --
// warp-per-row, W staged through smem in K=32 chunks, x broadcast via shfl.
template <int CIN, int COUT, bool RELU_IN>
__global__ void k_gemm(const float* __restrict__ x, const float* __restrict__ W,
                       const float* __restrict__ bias, float* __restrict__ out,
                       int n) {
    __shared__ float Ws[32 * COUT];
    const int warp = threadIdx.x >> 5;
    const int lane = threadIdx.x & 31;
    const int row = blockIdx.x * 8 + warp;

    float acc[COUT / 32];
#pragma unroll
    for (int j = 0; j < COUT / 32; j++) acc[j] = 0.0f;

    for (int k0 = 0; k0 < CIN; k0 += 32) {
        __syncthreads();
        for (int idx = threadIdx.x; idx < 32 * COUT; idx += blockDim.x)
            Ws[idx] = W[(size_t)(k0 + idx / COUT) * COUT + (idx % COUT)];
        __syncthreads();

        float xv = 0.0f;
        if (row < n) {
            xv = x[(size_t)row * CIN + k0 + lane];
            if (RELU_IN) xv = fmaxf(xv, 0.0f);
        }
#pragma unroll
        for (int k = 0; k < 32; k++) {
            float xb = __shfl_sync(0xffffffffu, xv, k);
#pragma unroll
            for (int j = 0; j < COUT / 32; j++)
                acc[j] = fmaf(xb, Ws[k * COUT + lane + 32 * j], acc[j]);
        }
    }

    if (row < n) {
#pragma unroll
        for (int j = 0; j < COUT / 32; j++) {
            float v = acc[j];
            if (bias) v += bias[lane + 32 * j];
            out[(size_t)row * COUT + lane + 32 * j] = v;
        }
    }
}

// ---------------- aggregation init: bias + self-loop term -----------------
template <int C>
__global__ void k_agg_init(float* __restrict__ out, const float* __restrict__ h,
                           const float* __restrict__ bias, int n) {
    int t = blockIdx.x * blockDim.x + threadIdx.x;
    if (t < n * C) {
        int i = t / C, c = t % C;
        float di = g_dinv[i];
        out[t] = bias[c] + di * di * h[t];
    }
}

// ---------------- aggregation edges: out[dst] += w * h[src] ---------------
// C/4 lanes per edge, float4 gather + vectorized red.global.add.v4.f32
__device__ __forceinline__ void red_add_v4(float* p, float4 v) {
    asm volatile("red.global.add.v4.f32 [%0], {%1,%2,%3,%4};" ::"l"(p),
                 "f"(v.x), "f"(v.y), "f"(v.z), "f"(v.w)
                 : "memory");
}

template <int C>
__global__ void k_agg_edges(float* __restrict__ out, const float* __restrict__ h,
                            const int* __restrict__ src,
                            const int* __restrict__ dst, int e) {
    const int LPE = C / 4;  // lanes per edge
    int t = blockIdx.x * blockDim.x + threadIdx.x;
    int eid = t / LPE;
    int lane = t % LPE;
    if (eid >= e) return;
    int s = src[eid];
    int d = dst[eid];
    float w = g_dinv[s] * g_dinv[d];
    const float4* hp = reinterpret_cast<const float4*>(h + (size_t)s * C);
    float4 v = hp[lane];
    v.x *= w; v.y *= w; v.z *= w; v.w *= w;
    red_add_v4(out + (size_t)d * C + lane * 4, v);
}

// ---------------- reparameterize ----------------
__global__ void k_z(const float* __restrict__ mu, const float* __restrict__ lv,
                    const float* __restrict__ eps, float* __restrict__ z,
                    int total) {
    int t = blockIdx.x * blockDim.x + threadIdx.x;
    if (t < total) z[t] = mu[t] + eps[t] * expf(0.5f * lv[t]);
}

// ---------------- launch ----------------
extern "C" void kernel_launch(void* const* d_in, const int* in_sizes, int n_in,
                              void* d_out, int out_size) {
    const float* x    = (const float*)d_in[0];
    const int*   ei   = (const int*)d_in[1];
    const float* eps  = (const float*)d_in[2];
    const float* W_e1 = (const float*)d_in[3];
    const float* b_e1 = (const float*)d_in[4];
    const float* W_e2 = (const float*)d_in[5];
    const float* b_e2 = (const float*)d_in[6];
    const float* W_mu = (const float*)d_in[7];
    const float* b_mu = (const float*)d_in[8];
    const float* W_lv = (const float*)d_in[9];
    const float* b_lv = (const float*)d_in[10];
    const float* W_d1 = (const float*)d_in[11];
    const float* b_d1 = (const float*)d_in[12];
    const float* W_d2 = (const float*)d_in[13];
    const float* b_d2 = (const float*)d_in[14];

    const int n = in_sizes[0] / IC;   // 50000
    const int e = in_sizes[1] / 2;    // 800000
    const int* src = ei;
    const int* dst = ei + e;

    float *h, *a, *z;
    cudaGetSymbolAddress((void**)&h, g_h);
    cudaGetSymbolAddress((void**)&a, g_a);
    cudaGetSymbolAddress((void**)&z, g_z);

    float* out_d  = (float*)d_out;
    float* out_mu = out_d + (size_t)n * IC;
    float* out_lv = out_mu + (size_t)n * OC;

    const int T = 256;
    auto cdiv = [](long long v, int b) { return (int)((v + b - 1) / b); };

    // normalization
    k_deg_init<<<cdiv(n, T), T>>>(n);
    k_deg_count<<<cdiv(e, T), T>>>(dst, e);
    k_dinv<<<cdiv(n, T), T>>>(n);

    // encoder conv1: x[128] -> 128, relu deferred to next gemm read
    k_gemm<128, 128, false><<<cdiv(n, 8), T>>>(x, W_e1, nullptr, h, n);
    k_agg_init<128><<<cdiv((long long)n * 128, T), T>>>(a, h, b_e1, n);
    k_agg_edges<128><<<cdiv((long long)e * 32, T), T>>>(a, h, src, dst, e);

    // encoder conv2: relu(a)[128] -> 64
    k_gemm<128, 64, true><<<cdiv(n, 8), T>>>(a, W_e2, nullptr, h, n);
    k_agg_init<64><<<cdiv((long long)n * 64, T), T>>>(a, h, b_e2, n);
    k_agg_edges<64><<<cdiv((long long)e * 16, T), T>>>(a, h, src, dst, e);

    // mu / logvar straight into output, then z
    k_gemm<64, 64, false><<<cdiv(n, 8), T>>>(a, W_mu, b_mu, out_mu, n);
    k_gemm<64, 64, false><<<cdiv(n, 8), T>>>(a, W_lv, b_lv, out_lv, n);
    k_z<<<cdiv((long long)n * 64, T), T>>>(out_mu, out_lv, eps, z, n * 64);

    // decoder conv1: z[64] -> 128, relu deferred
    k_gemm<64, 128, false><<<cdiv(n, 8), T>>>(z, W_d1, nullptr, h, n);
    k_agg_init<128><<<cdiv((long long)n * 128, T), T>>>(a, h, b_d1, n);
    k_agg_edges<128><<<cdiv((long long)e * 32, T), T>>>(a, h, src, dst, e);

    // decoder conv2: relu(a)[128] -> 128, aggregate directly into d_out
    k_gemm<128, 128, true><<<cdiv(n, 8), T>>>(a, W_d2, nullptr, h, n);
    k_agg_init<128><<<cdiv((long long)n * 128, T), T>>>(out_d, h, b_d2, n);
    k_agg_edges<128><<<cdiv((long long)e * 32, T), T>>>(out_d, h, src, dst, e);
}

// round 7
// speedup vs baseline: 1.6405x; 1.6405x over previous
#include <cuda_runtime.h>
#include <cstdint>

#define NN 50000
#define IC 128
#define OC 64

typedef unsigned long long u64;

// ---------------- device scratch (static, allocation-free) ----------------
__device__ float g_dinv[NN];
__device__ float g_h[(size_t)NN * 128];
__device__ float g_a[(size_t)NN * 128];
__device__ float g_z[(size_t)NN * 64];
__device__ float g_mulv[(size_t)NN * 128];
__device__ float g_Wmulv[64 * 128];
__device__ float g_bmulv[128];

// ---------------- f32x2 helpers (Blackwell packed fp32 FMA) ----------------
__device__ __forceinline__ u64 pack2(float v) {
    u64 r;
    asm("mov.b64 %0, {%1, %2};" : "=l"(r) : "r"(__float_as_uint(v)), "r"(__float_as_uint(v)));
    return r;
}
__device__ __forceinline__ void unpack2(u64 v, float& lo, float& hi) {
    unsigned a, b;
    asm("mov.b64 {%0, %1}, %2;" : "=r"(a), "=r"(b) : "l"(v));
    lo = __uint_as_float(a); hi = __uint_as_float(b);
}
__device__ __forceinline__ void ffma2(u64& d, u64 a, u64 b) {
    asm("fma.rn.f32x2 %0, %1, %2, %0;" : "+l"(d) : "l"(a), "l"(b));
}

// ---------------- degree / normalization ----------------
__global__ void k_deg_init(int n) {
    int i = blockIdx.x * blockDim.x + threadIdx.x;
    if (i < n) g_dinv[i] = 1.0f;
}
__global__ void k_deg_count(const int* __restrict__ dst, int e) {
    int i = blockIdx.x * blockDim.x + threadIdx.x;
    if (i < e) atomicAdd(&g_dinv[dst[i]], 1.0f);
}
__global__ void k_dinv(int n) {
    int i = blockIdx.x * blockDim.x + threadIdx.x;
    if (i < n) g_dinv[i] = rsqrtf(g_dinv[i]);
}

// ---------------- pack W_mu|W_lv into one 64->128 GEMM ----------------
__global__ void k_pack_mulv(const float* __restrict__ Wmu, const float* __restrict__ Wlv,
                            const float* __restrict__ bmu, const float* __restrict__ blv) {
    int i = blockIdx.x * blockDim.x + threadIdx.x;
    if (i < 64 * 128) {
        int k = i >> 7, c = i & 127;
        g_Wmulv[i] = (c < 64) ? Wmu[k * 64 + c] : Wlv[k * 64 + c - 64];
    }
    if (i < 128) g_bmulv[i] = (i < 64) ? bmu[i] : blv[i - 64];
}

// ---------------- register-tiled GEMM with f32x2 ----------------
// out[n,COUT] = act(x)[n,CIN] @ W[CIN,COUT]
// AGG epilogue: out_h = acc ; out_a = bias + dinv[row]^2 * acc
// else:         out_h = acc + bias
// BM=128 rows per CTA, 256 threads: 16 tx (N) x 16 ty (M), TM=8 (rows ty+16i), TN=COUT/16.
template <int CIN, int COUT, bool RELU_IN, bool AGG>
__global__ __launch_bounds__(256, 1) void k_gemm(
    const float* __restrict__ x, const float* __restrict__ W,
    const float* __restrict__ bias, float* __restrict__ out_h,
    float* __restrict__ out_a, int n) {
    constexpr int BM = 128;
    constexpr int TM = 8;
    constexpr int TN = COUT / 16;
    constexpr int CINP = CIN + 4;  // pad: row stride % 32 banks = 4 -> conflict-free scalar reads

    extern __shared__ float sm[];
    float* Ws = sm;                   // [CIN][COUT]
    float* As = sm + CIN * COUT;      // [BM][CINP]

    const int tid = threadIdx.x;
    const int tx = tid & 15;          // N dim
    const int ty = tid >> 4;          // M dim
    const int row0 = blockIdx.x * BM;

    // stage W (L2-hot, contiguous float4)
    {
        const float4* Wg = (const float4*)W;
        float4* Wsv = (float4*)Ws;
        #pragma unroll 4
        for (int i = tid; i < CIN * COUT / 4; i += 256) Wsv[i] = Wg[i];
    }
    // stage x tile with optional relu; out-of-range rows -> 0
    {
        constexpr int K4 = CIN / 4;
        #pragma unroll 4
        for (int i = tid; i < BM * K4; i += 256) {
            int r = i / K4, k4 = i % K4;
            float4 v = make_float4(0.f, 0.f, 0.f, 0.f);
            int rg = row0 + r;
            if (rg < n) {
                v = ((const float4*)(x + (size_t)rg * CIN))[k4];
                if (RELU_IN) {
                    v.x = fmaxf(v.x, 0.f); v.y = fmaxf(v.y, 0.f);
                    v.z = fmaxf(v.z, 0.f); v.w = fmaxf(v.w, 0.f);
                }
            }
            float* d = &As[r * CINP + k4 * 4];
            d[0] = v.x; d[1] = v.y; d[2] = v.z; d[3] = v.w;
        }
    }
    __syncthreads();

    u64 acc[TM][TN / 2];
    #pragma unroll
    for (int i = 0; i < TM; i++)
        #pragma unroll
        for (int j = 0; j < TN / 2; j++) acc[i][j] = 0ull;

    const float* Bp = Ws + tx * TN;
    #pragma unroll 8
    for (int k = 0; k < CIN; k++) {
        u64 a2[TM];
        #pragma unroll
        for (int i = 0; i < TM; i++) a2[i] = pack2(As[(ty + 16 * i) * CINP + k]);
        #pragma unroll
        for (int j4 = 0; j4 < TN / 4; j4++) {
            ulonglong2 bb = *(const ulonglong2*)(Bp + k * COUT + j4 * 4);
            #pragma unroll
            for (int i = 0; i < TM; i++) {
                ffma2(acc[i][j4 * 2 + 0], a2[i], bb.x);
                ffma2(acc[i][j4 * 2 + 1], a2[i], bb.y);
            }
        }
    }

    // epilogue
    #pragma unroll
    for (int i = 0; i < TM; i++) {
        int rg = row0 + ty + 16 * i;
        if (rg >= n) continue;
        float dsq = 0.f;
        if (AGG) { float di = g_dinv[rg]; dsq = di * di; }
        #pragma unroll
        for (int j = 0; j < TN / 2; j++) {
            float c0, c1;
            unpack2(acc[i][j], c0, c1);
            int col = tx * TN + j * 2;
            if (AGG) {
                *(float2*)(out_h + (size_t)rg * COUT + col) = make_float2(c0, c1);
                *(float2*)(out_a + (size_t)rg * COUT + col) =
                    make_float2(bias[col] + dsq * c0, bias[col + 1] + dsq * c1);
            } else {
                *(float2*)(out_h + (size_t)rg * COUT + col) =
                    make_float2(c0 + bias[col], c1 + bias[col + 1]);
            }
        }
    }
}

// ---------------- aggregation edges: out[dst] += w * h[src] ---------------
__device__ __forceinline__ void red_add_v4(float* p, float4 v) {
    asm volatile("red.global.add.v4.f32 [%0], {%1,%2,%3,%4};" ::"l"(p),
                 "f"(v.x), "f"(v.y), "f"(v.z), "f"(v.w)
                 : "memory");
}

template <int C>
__global__ void k_agg_edges(float* __restrict__ out, const float* __restrict__ h,
                            const int* __restrict__ src,
                            const int* __restrict__ dst, int e) {
    const int LPE = C / 4;
    int t = blockIdx.x * blockDim.x + threadIdx.x;
    int eid = t / LPE;
    int lane = t % LPE;
    if (eid >= e) return;
    int s = src[eid];
    int d = dst[eid];
    float w = g_dinv[s] * g_dinv[d];
    const float4* hp = reinterpret_cast<const float4*>(h + (size_t)s * C);
    float4 v = hp[lane];
    v.x *= w; v.y *= w; v.z *= w; v.w *= w;
    red_add_v4(out + (size_t)d * C + lane * 4, v);
}

// ---------------- mu / logvar split + reparameterize ----------------
__global__ void k_z(const float* __restrict__ mulv, const float* __restrict__ eps,
                    float* __restrict__ out_mu, float* __restrict__ out_lv,
                    float* __restrict__ z, int n) {
    int t = blockIdx.x * blockDim.x + threadIdx.x;
    if (t < n * 64) {
        int r = t >> 6, c = t & 63;
        float mu = mulv[(size_t)r * 128 + c];
        float lv = mulv[(size_t)r * 128 + 64 + c];
        out_mu[t] = mu;
        out_lv[t] = lv;
        z[t] = mu + eps[t] * expf(0.5f * lv);
    }
}

// ---------------- launch ----------------
extern "C" void kernel_launch(void* const* d_in, const int* in_sizes, int n_in,
                              void* d_out, int out_size) {
    const float* x    = (const float*)d_in[0];
    const int*   ei   = (const int*)d_in[1];
    const float* eps  = (const float*)d_in[2];
    const float* W_e1 = (const float*)d_in[3];
    const float* b_e1 = (const float*)d_in[4];
    const float* W_e2 = (const float*)d_in[5];
    const float* b_e2 = (const float*)d_in[6];
    const float* W_mu = (const float*)d_in[7];
    const float* b_mu = (const float*)d_in[8];
    const float* W_lv = (const float*)d_in[9];
    const float* b_lv = (const float*)d_in[10];
    const float* W_d1 = (const float*)d_in[11];
    const float* b_d1 = (const float*)d_in[12];
    const float* W_d2 = (const float*)d_in[13];
    const float* b_d2 = (const float*)d_in[14];

    const int n = in_sizes[0] / IC;  // 50000
    const int e = in_sizes[1] / 2;   // 800000
    const int* src = ei;
    const int* dst = ei + e;

    float *h, *a, *z, *mulv, *Wmlv, *bmlv;
    cudaGetSymbolAddress((void**)&h, g_h);
    cudaGetSymbolAddress((void**)&a, g_a);
    cudaGetSymbolAddress((void**)&z, g_z);
    cudaGetSymbolAddress((void**)&mulv, g_mulv);
    cudaGetSymbolAddress((void**)&Wmlv, g_Wmulv);
    cudaGetSymbolAddress((void**)&bmlv, g_bmulv);

    float* out_d  = (float*)d_out;
    float* out_mu = out_d + (size_t)n * IC;
    float* out_lv = out_mu + (size_t)n * OC;

    const int T = 256;
    auto cdiv = [](long long v, int b) { return (int)((v + b - 1) / b); };

    // dynamic smem sizes per instantiation
    const int SM_128_128 = (128 * 128 + 128 * 132) * 4;  // 133,120 B
    const int SM_128_64  = (128 * 64 + 128 * 132) * 4;   // 100,352 B
    const int SM_64_128  = (64 * 128 + 128 * 68) * 4;    //  67,584 B
    cudaFuncSetAttribute(k_gemm<128, 128, false, true>, cudaFuncAttributeMaxDynamicSharedMemorySize, SM_128_128);
    cudaFuncSetAttribute(k_gemm<128, 128, true, true>,  cudaFuncAttributeMaxDynamicSharedMemorySize, SM_128_128);
    cudaFuncSetAttribute(k_gemm<128, 64, true, true>,   cudaFuncAttributeMaxDynamicSharedMemorySize, SM_128_64);
    cudaFuncSetAttribute(k_gemm<64, 128, false, true>,  cudaFuncAttributeMaxDynamicSharedMemorySize, SM_64_128);
    cudaFuncSetAttribute(k_gemm<64, 128, false, false>, cudaFuncAttributeMaxDynamicSharedMemorySize, SM_64_128);

    const int GG = cdiv(n, 128);  // 391 CTAs

    // normalization + weight packing (independent prep)
    k_deg_init<<<cdiv(n, T), T>>>(n);
    k_deg_count<<<cdiv(e, T), T>>>(dst, e);
    k_dinv<<<cdiv(n, T), T>>>(n);
    k_pack_mulv<<<cdiv(64 * 128, T), T>>>(W_mu, W_lv, b_mu, b_lv);

    // encoder conv1: x[128] -> 128 (epilogue seeds a = b + dinv^2 h)
    k_gemm<128, 128, false, true><<<GG, T, SM_128_128>>>(x, W_e1, b_e1, h, a, n);
    k_agg_edges<128><<<cdiv((long long)e * 32, T), T>>>(a, h, src, dst, e);

    // encoder conv2: relu(a)[128] -> 64
    k_gemm<128, 64, true, true><<<GG, T, SM_128_64>>>(a, W_e2, b_e2, h, a, n);
    k_agg_edges<64><<<cdiv((long long)e * 16, T), T>>>(a, h, src, dst, e);

    // mu|logvar fused 64 -> 128, then reparameterize
    k_gemm<64, 128, false, false><<<GG, T, SM_64_128>>>(a, Wmlv, bmlv, mulv, nullptr, n);
    k_z<<<cdiv((long long)n * 64, T), T>>>(mulv, eps, out_mu, out_lv, z, n);

    // decoder conv1: z[64] -> 128
    k_gemm<64, 128, false, true><<<GG, T, SM_64_128>>>(z, W_d1, b_d1, h, a, n);
    k_agg_edges<128><<<cdiv((long long)e * 32, T), T>>>(a, h, src, dst, e);

    // decoder conv2: relu(a)[128] -> 128, aggregate into d_out
    k_gemm<128, 128, true, true><<<GG, T, SM_128_128>>>(a, W_d2, b_d2, h, out_d, n);
    k_agg_edges<128><<<cdiv((long long)e * 32, T), T>>>(out_d, h, src, dst, e);
}

// round 9
// speedup vs baseline: 1.9930x; 1.2149x over previous
#include <cuda_runtime.h>
#include <cstdint>

#define NN 50000
#define EE 800000
#define IC 128
#define OC 64

typedef unsigned long long u64;

// ---------------- device scratch (static, allocation-free) ----------------
__device__ float g_dinv[NN];
__device__ int   g_degcnt[NN];
__device__ int   g_rowptr[NN + 1];
__device__ int   g_cursor[NN];
__device__ int   g_col[EE];
__device__ float g_wgt[EE];
__device__ float g_h[(size_t)NN * 128];
__device__ float g_a[(size_t)NN * 128];
__device__ float g_z[(size_t)NN * 64];

// ---------------- f32x2 helpers ----------------
__device__ __forceinline__ u64 pack2(float v) {
    u64 r;
    asm("mov.b64 %0, {%1, %2};" : "=l"(r) : "r"(__float_as_uint(v)), "r"(__float_as_uint(v)));
    return r;
}
__device__ __forceinline__ void unpack2(u64 v, float& lo, float& hi) {
    unsigned a, b;
    asm("mov.b64 {%0, %1}, %2;" : "=r"(a), "=r"(b) : "l"(v));
    lo = __uint_as_float(a); hi = __uint_as_float(b);
}
__device__ __forceinline__ void ffma2(u64& d, u64 a, u64 b) {
    asm("fma.rn.f32x2 %0, %1, %2, %0;" : "+l"(d) : "l"(a), "l"(b));
}

// ---------------- CSR build ----------------
__global__ void k_zero_deg(int n) {
    int i = blockIdx.x * blockDim.x + threadIdx.x;
    if (i < n) g_degcnt[i] = 0;
}
__global__ void k_deg_count(const int* __restrict__ dst, int e) {
    int i = blockIdx.x * blockDim.x + threadIdx.x;
    if (i < e) atomicAdd(&g_degcnt[dst[i]], 1);
}

// single-block exclusive scan over n degree counts -> rowptr/cursor, plus dinv
__global__ __launch_bounds__(1024) void k_scan(int n, int e) {
    __shared__ int warp_sums[32];
    __shared__ int warp_off[32];
    const int tid = threadIdx.x;
    const int lane = tid & 31;
    const int wid = tid >> 5;
    const int chunk = (n + 1023) / 1024;
    const int base = tid * chunk;
    const int lim = min(base + chunk, n);

    int s = 0;
    for (int i = base; i < lim; i++) s += g_degcnt[i];

    // inclusive warp scan
    int v = s;
    #pragma unroll
    for (int o = 1; o < 32; o <<= 1) {
        int t = __shfl_up_sync(0xffffffffu, v, o);
        if (lane >= o) v += t;
    }
    if (lane == 31) warp_sums[wid] = v;
    __syncthreads();
    if (wid == 0) {
        int w = (lane < 32) ? warp_sums[lane] : 0;
        #pragma unroll
        for (int o = 1; o < 32; o <<= 1) {
            int t = __shfl_up_sync(0xffffffffu, w, o);
            if (lane >= o) w += t;
        }
        warp_off[lane] = w;
    }
    __syncthreads();

    int off = v - s + (wid ? warp_off[wid - 1] : 0);  // exclusive prefix for this thread
    int run = off;
    for (int i = base; i < lim; i++) {
        g_rowptr[i] = run;
        g_cursor[i] = run;
        run += g_degcnt[i];
        g_dinv[i] = rsqrtf((float)g_degcnt[i] + 1.0f);  // +1 self-loop
    }
    if (tid == 0) g_rowptr[n] = e;
}

__global__ void k_scatter(const int* __restrict__ src, const int* __restrict__ dst, int e) {
    int i = blockIdx.x * blockDim.x + threadIdx.x;
    if (i < e) {
        int s = src[i], d = dst[i];
        int pos = atomicAdd(&g_cursor[d], 1);
        g_col[pos] = s;
        g_wgt[pos] = g_dinv[s] * g_dinv[d];
    }
}

// ---------------- register-tiled GEMM with f32x2 (writes raw h) ----------
template <int CIN, int COUT, bool RELU_IN>
__global__ __launch_bounds__(256, 1) void k_gemm(
    const float* __restrict__ x, const float* __restrict__ W,
    float* __restrict__ out_h, int n) {
    constexpr int BM = 128;
    constexpr int TM = 8;
    constexpr int TN = COUT / 16;
    constexpr int CINP = CIN + 4;

    extern __shared__ float sm[];
    float* Ws = sm;
    float* As = sm + CIN * COUT;

    const int tid = threadIdx.x;
    const int tx = tid & 15;
    const int ty = tid >> 4;
    const int row0 = blockIdx.x * BM;

    {
        const float4* Wg = (const float4*)W;
        float4* Wsv = (float4*)Ws;
        #pragma unroll 4
        for (int i = tid; i < CIN * COUT / 4; i += 256) Wsv[i] = Wg[i];
    }
    {
        constexpr int K4 = CIN / 4;
        #pragma unroll 4
        for (int i = tid; i < BM * K4; i += 256) {
            int r = i / K4, k4 = i % K4;
            float4 v = make_float4(0.f, 0.f, 0.f, 0.f);
            int rg = row0 + r;
            if (rg < n) {
                v = ((const float4*)(x + (size_t)rg * CIN))[k4];
                if (RELU_IN) {
                    v.x = fmaxf(v.x, 0.f); v.y = fmaxf(v.y, 0.f);
                    v.z = fmaxf(v.z, 0.f); v.w = fmaxf(v.w, 0.f);
                }
            }
            float* d = &As[r * CINP + k4 * 4];
            d[0] = v.x; d[1] = v.y; d[2] = v.z; d[3] = v.w;
        }
    }
    __syncthreads();

    u64 acc[TM][TN / 2];
    #pragma unroll
    for (int i = 0; i < TM; i++)
        #pragma unroll
        for (int j = 0; j < TN / 2; j++) acc[i][j] = 0ull;

    const float* Bp = Ws + tx * TN;
    #pragma unroll 8
    for (int k = 0; k < CIN; k++) {
        u64 a2[TM];
        #pragma unroll
        for (int i = 0; i < TM; i++) a2[i] = pack2(As[(ty + 16 * i) * CINP + k]);
        #pragma unroll
        for (int j4 = 0; j4 < TN / 4; j4++) {
            ulonglong2 bb = *(const ulonglong2*)(Bp + k * COUT + j4 * 4);
            #pragma unroll
            for (int i = 0; i < TM; i++) {
                ffma2(acc[i][j4 * 2 + 0], a2[i], bb.x);
                ffma2(acc[i][j4 * 2 + 1], a2[i], bb.y);
            }
        }
    }

    #pragma unroll
    for (int i = 0; i < TM; i++) {
        int rg = row0 + ty + 16 * i;
        if (rg >= n) continue;
        #pragma unroll
        for (int j = 0; j < TN / 2; j++) {
            float c0, c1;
            unpack2(acc[i][j], c0, c1);
            int col = tx * TN + j * 2;
            *(float2*)(out_h + (size_t)rg * COUT + col) = make_float2(c0, c1);
        }
    }
}

// ---------------- mu|lv GEMM: 64 -> (64|64) straight into d_out ----------
__global__ __launch_bounds__(256, 1) void k_gemm_mulv(
    const float* __restrict__ x,
    const float* __restrict__ Wmu, const float* __restrict__ Wlv,
    const float* __restrict__ bmu, const float* __restrict__ blv,
    float* __restrict__ out_mu, float* __restrict__ out_lv, int n) {
    constexpr int CIN = 64, COUT = 128, BM = 128, TM = 8, TN = 8, CINP = CIN + 4;

    extern __shared__ float sm[];
    float* Ws = sm;                 // [64][128]: cols 0-63 mu, 64-127 lv
    float* As = sm + CIN * COUT;

    const int tid = threadIdx.x;
    const int tx = tid & 15;
    const int ty = tid >> 4;
    const int row0 = blockIdx.x * BM;

    for (int i = tid; i < CIN * COUT / 4; i += 256) {
        int k = (i * 4) >> 7, c = (i * 4) & 127;
        const float* srcW = (c < 64) ? (Wmu + k * 64 + c) : (Wlv + k * 64 + c - 64);
        ((float4*)Ws)[i] = *(const float4*)srcW;
    }
    {
        constexpr int K4 = CIN / 4;
        for (int i = tid; i < BM * K4; i += 256) {
            int r = i / K4, k4 = i % K4;
            float4 v = make_float4(0.f, 0.f, 0.f, 0.f);
            int rg = row0 + r;
            if (rg < n) v = ((const float4*)(x + (size_t)rg * CIN))[k4];
            float* d = &As[r * CINP + k4 * 4];
            d[0] = v.x; d[1] = v.y; d[2] = v.z; d[3] = v.w;
        }
    }
    __syncthreads();

    u64 acc[TM][TN / 2];
    #pragma unroll
    for (int i = 0; i < TM; i++)
        #pragma unroll
        for (int j = 0; j < TN / 2; j++) acc[i][j] = 0ull;

    const float* Bp = Ws + tx * TN;
    #pragma unroll 8
    for (int k = 0; k < CIN; k++) {
        u64 a2[TM];
        #pragma unroll
        for (int i = 0; i < TM; i++) a2[i] = pack2(As[(ty + 16 * i) * CINP + k]);
        #pragma unroll
        for (int j4 = 0; j4 < TN / 4; j4++) {
            ulonglong2 bb = *(const ulonglong2*)(Bp + k * COUT + j4 * 4);
            #pragma unroll
            for (int i = 0; i < TM; i++) {
                ffma2(acc[i][j4 * 2 + 0], a2[i], bb.x);
                ffma2(acc[i][j4 * 2 + 1], a2[i], bb.y);
            }
        }
    }

    #pragma unroll
    for (int i = 0; i < TM; i++) {
        int rg = row0 + ty + 16 * i;
        if (rg >= n) continue;
        #pragma unroll
        for (int j = 0; j < TN / 2; j++) {
            float c0, c1;
            unpack2(acc[i][j], c0, c1);
            int col = tx * TN + j * 2;
            if (col < 64) {
                c0 += bmu[col]; c1 += bmu[col + 1];
                *(float2*)(out_mu + (size_t)rg * 64 + col) = make_float2(c0, c1);
            } else {
                int cl = col - 64;
                c0 += blv[cl]; c1 += blv[cl + 1];
                *(float2*)(out_lv + (size_t)rg * 64 + cl) = make_float2(c0, c1);
            }
        }
    }
}

// ---------------- CSR aggregation: warp per dst row, no atomics ----------
__global__ __launch_bounds__(256) void k_agg_csr128(
    const float* __restrict__ h, const float* __restrict__ bias,
    float* __restrict__ out, int n) {
    int warp = (blockIdx.x * blockDim.x + threadIdx.x) >> 5;
    int lane = threadIdx.x & 31;
    if (warp >= n) return;
    const float4* h4 = (const float4*)h;
    float4 b = ((const float4*)bias)[lane];
    float di = g_dinv[warp];
    float d2 = di * di;
    float4 hv = h4[(size_t)warp * 32 + lane];
    float4 acc0 = make_float4(b.x + d2 * hv.x, b.y + d2 * hv.y,
                              b.z + d2 * hv.z, b.w + d2 * hv.w);
    float4 acc1 = make_float4(0.f, 0.f, 0.f, 0.f);

    int beg = g_rowptr[warp], end = g_rowptr[warp + 1];
    for (int j0 = beg; j0 < end; j0 += 32) {
        int jj = j0 + lane;
        int s = 0; float w = 0.f;
        if (jj < end) { s = g_col[jj]; w = g_wgt[jj]; }
        int cnt = min(32, end - j0);
        #pragma unroll 4
        for (int t = 0; t < cnt; t++) {
            int ss = __shfl_sync(0xffffffffu, s, t);
            float ww = __shfl_sync(0xffffffffu, w, t);
            float4 x4 = h4[(size_t)ss * 32 + lane];
            if (t & 1) {
                acc1.x = fmaf(ww, x4.x, acc1.x); acc1.y = fmaf(ww, x4.y, acc1.y);
                acc1.z = fmaf(ww, x4.z, acc1.z); acc1.w = fmaf(ww, x4.w, acc1.w);
            } else {
                acc0.x = fmaf(ww, x4.x, acc0.x); acc0.y = fmaf(ww, x4.y, acc0.y);
                acc0.z = fmaf(ww, x4.z, acc0.z); acc0.w = fmaf(ww, x4.w, acc0.w);
            }
        }
    }
    acc0.x += acc1.x; acc0.y += acc1.y; acc0.z += acc1.z; acc0.w += acc1.w;
    ((float4*)out)[(size_t)warp * 32 + lane] = acc0;
}

__global__ __launch_bounds__(256) void k_agg_csr64(
    const float* __restrict__ h, const float* __restrict__ bias,
    float* __restrict__ out, int n) {
    int warp = (blockIdx.x * blockDim.x + threadIdx.x) >> 5;
    int lane = threadIdx.x & 31;
    if (warp >= n) return;
    const float2* h2 = (const float2*)h;
    float2 b = ((const float2*)bias)[lane];
    float di = g_dinv[warp];
    float d2 = di * di;
    float2 hv = h2[(size_t)warp * 32 + lane];
    float2 acc0 = make_float2(b.x + d2 * hv.x, b.y + d2 * hv.y);
    float2 acc1 = make_float2(0.f, 0.f);

    int beg = g_rowptr[warp], end = g_rowptr[warp + 1];
    for (int j0 = beg; j0 < end; j0 += 32) {
        int jj = j0 + lane;
        int s = 0; float w = 0.f;
        if (jj < end) { s = g_col[jj]; w = g_wgt[jj]; }
        int cnt = min(32, end - j0);
        #pragma unroll 4
        for (int t = 0; t < cnt; t++) {
            int ss = __shfl_sync(0xffffffffu, s, t);
            float ww = __shfl_sync(0xffffffffu, w, t);
            float2 x2 = h2[(size_t)ss * 32 + lane];
            if (t & 1) {
                acc1.x = fmaf(ww, x2.x, acc1.x); acc1.y = fmaf(ww, x2.y, acc1.y);
            } else {
                acc0.x = fmaf(ww, x2.x, acc0.x); acc0.y = fmaf(ww, x2.y, acc0.y);
            }
        }
    }
    acc0.x += acc1.x; acc0.y += acc1.y;
    ((float2*)out)[(size_t)warp * 32 + lane] = acc0;
}

// ---------------- reparameterize (reads mu/lv straight from d_out) -------
__global__ void k_z(const float* __restrict__ mu, const float* __restrict__ lv,
                    const float* __restrict__ eps, float* __restrict__ z, int total) {
    int t = blockIdx.x * blockDim.x + threadIdx.x;
    if (t < total) z[t] = mu[t] + eps[t] * expf(0.5f * lv[t]);
}

// ---------------- launch ----------------
extern "C" void kernel_launch(void* const* d_in, const int* in_sizes, int n_in,
                              void* d_out, int out_size) {
    const float* x    = (const float*)d_in[0];
    const int*   ei   = (const int*)d_in[1];
    const float* eps  = (const float*)d_in[2];
    const float* W_e1 = (const float*)d_in[3];
    const float* b_e1 = (const float*)d_in[4];
    const float* W_e2 = (const float*)d_in[5];
    const float* b_e2 = (const float*)d_in[6];
    const float* W_mu = (const float*)d_in[7];
    const float* b_mu = (const float*)d_in[8];
    const float* W_lv = (const float*)d_in[9];
    const float* b_lv = (const float*)d_in[10];
    const float* W_d1 = (const float*)d_in[11];
    const float* b_d1 = (const float*)d_in[12];
    const float* W_d2 = (const float*)d_in[13];
    const float* b_d2 = (const float*)d_in[14];

    const int n = in_sizes[0] / IC;  // 50000
    const int e = in_sizes[1] / 2;   // 800000
    const int* src = ei;
    const int* dst = ei + e;

    float *h, *a, *z;
    cudaGetSymbolAddress((void**)&h, g_h);
    cudaGetSymbolAddress((void**)&a, g_a);
    cudaGetSymbolAddress((void**)&z, g_z);

    float* out_d  = (float*)d_out;
    float* out_mu = out_d + (size_t)n * IC;
    float* out_lv = out_mu + (size_t)n * OC;

    const int T = 256;
    auto cdiv = [](long long v, int b) { return (int)((v + b - 1) / b); };

    const int SM_128_128 = (128 * 128 + 128 * 132) * 4;
    const int SM_128_64  = (128 * 64 + 128 * 132) * 4;
    const int SM_64_128  = (64 * 128 + 128 * 68) * 4;
    cudaFuncSetAttribute(k_gemm<128, 128, false>, cudaFuncAttributeMaxDynamicSharedMemorySize, SM_128_128);
    cudaFuncSetAttribute(k_gemm<128, 128, true>,  cudaFuncAttributeMaxDynamicSharedMemorySize, SM_128_128);
    cudaFuncSetAttribute(k_gemm<128, 64, true>,   cudaFuncAttributeMaxDynamicSharedMemorySize, SM_128_64);
    cudaFuncSetAttribute(k_gemm<64, 128, false>,  cudaFuncAttributeMaxDynamicSharedMemorySize, SM_64_128);
    cudaFuncSetAttribute(k_gemm_mulv,             cudaFuncAttributeMaxDynamicSharedMemorySize, SM_64_128);

    const int GG = cdiv(n, 128);            // GEMM grid
    const int GA = cdiv((long long)n * 32, T);  // agg grid (warp per row)

    // CSR build
    k_zero_deg<<<cdiv(n, T), T>>>(n);
    k_deg_count<<<cdiv(e, T), T>>>(dst, e);
    k_scan<<<1, 1024>>>(n, e);
    k_scatter<<<cdiv(e, T), T>>>(src, dst, e);

    // encoder conv1: x[128] -> 128
    k_gemm<128, 128, false><<<GG, T, SM_128_128>>>(x, W_e1, h, n);
    k_agg_csr128<<<GA, T>>>(h, b_e1, a, n);

    // encoder conv2: relu(a)[128] -> 64
    k_gemm<128, 64, true><<<GG, T, SM_128_64>>>(a, W_e2, h, n);
    k_agg_csr64<<<GA, T>>>(h, b_e2, a, n);

    // mu|lv fused straight into d_out, then z
    k_gemm_mulv<<<GG, T, SM_64_128>>>(a, W_mu, W_lv, b_mu, b_lv, out_mu, out_lv, n);
    k_z<<<cdiv((long long)n * 64, T), T>>>(out_mu, out_lv, eps, z, n * 64);

    // decoder conv1: z[64] -> 128
    k_gemm<64, 128, false><<<GG, T, SM_64_128>>>(z, W_d1, h, n);
    k_agg_csr128<<<GA, T>>>(h, b_d1, a, n);

    // decoder conv2: relu(a)[128] -> 128, aggregate into d_out
    k_gemm<128, 128, true><<<GG, T, SM_128_128>>>(a, W_d2, h, n);
    k_agg_csr128<<<GA, T>>>(h, b_d2, out_d, n);
}